// round 10
// baseline (speedup 1.0000x reference)
#include <cuda_runtime.h>
#include <cuda_fp16.h>
#include <cstdint>
#include <cstddef>

#define DEVINL __device__ __forceinline__
using u32 = uint32_t;
using ull = unsigned long long;

constexpr int D  = 512;
constexpr int NC = 128;

constexpr int TILE_B   = 16384;            // one 128-row x 128B packed tile (hi|lo)
constexpr int STAGE_B  = 2 * TILE_B;       // A tile + B tile
constexpr int NSTAGE   = 3;
constexpr int LOOP_SMEM = NSTAGE * STAGE_B;            // 98304
constexpr int VQ_SMEM   = LOOP_SMEM + 512 + 4096 + 512;

__device__ float g_tvec[NC];               // ||c||^2 - 2 b.c
__device__ __align__(128) char g_xsplit[256][16][TILE_B];   // 64 MB
__device__ __align__(128) char g_wsplit[4][16][TILE_B];     // 1 MB
__device__ __align__(128) char g_esplit[16][TILE_B];        // 256 KB (E = CB@W, split)

// ---------------------------------------------------------------- helpers
DEVINL u32 smem_u32(const void* p) {
    u32 a;
    asm("{ .reg .u64 t; cvta.to.shared.u64 t, %1; cvt.u32.u64 %0, t; }"
        : "=r"(a) : "l"(p));
    return a;
}
DEVINL void ldsm4(u32& r0, u32& r1, u32& r2, u32& r3, u32 a) {
    asm volatile("ldmatrix.sync.aligned.m8n8.x4.shared.b16 {%0,%1,%2,%3}, [%4];"
                 : "=r"(r0), "=r"(r1), "=r"(r2), "=r"(r3) : "r"(a));
}
DEVINL void mma_f16(float c[4], const u32 a[4], const u32 b[2]) {
    asm volatile(
        "mma.sync.aligned.m16n8k16.row.col.f32.f16.f16.f32 "
        "{%0,%1,%2,%3},{%4,%5,%6,%7},{%8,%9},{%0,%1,%2,%3};"
        : "+f"(c[0]), "+f"(c[1]), "+f"(c[2]), "+f"(c[3])
        : "r"(a[0]), "r"(a[1]), "r"(a[2]), "r"(a[3]), "r"(b[0]), "r"(b[1]));
}
DEVINL u32 pack_h2(__half a, __half b) {
    __half2 h = __halves2half2(a, b);
    return *reinterpret_cast<u32*>(&h);
}
DEVINL void fsplit(float x, __half& h, __half& l) {
    h = __float2half_rn(x);
    l = __float2half_rn(x - __half2float(h));
}
DEVINL void cp16(u32 dst, const void* src) {
    asm volatile("cp.async.cg.shared.global [%0], [%1], 16;" :: "r"(dst), "l"(src));
}
DEVINL void cp_commit() { asm volatile("cp.async.commit_group;" ::: "memory"); }
DEVINL void cp_wait1()  { asm volatile("cp.async.wait_group 1;" ::: "memory"); }
DEVINL void cp_wait0()  { asm volatile("cp.async.wait_group 0;" ::: "memory"); }

// split 16 fp32 into 2 hi + 2 lo 16B chunks of a packed tile row.
// hi chunk c at ((c^e)<<4), lo at (((c^4)^e)<<4), e = row&7.
DEVINL void split16(const float4 v[4], char* drow, int c0, int e) {
    #pragma unroll
    for (int c2 = 0; c2 < 2; ++c2) {
        const float f[8] = { v[2*c2].x, v[2*c2].y, v[2*c2].z, v[2*c2].w,
                             v[2*c2+1].x, v[2*c2+1].y, v[2*c2+1].z, v[2*c2+1].w };
        __half hh[8], ll[8];
        #pragma unroll
        for (int j = 0; j < 8; ++j) fsplit(f[j], hh[j], ll[j]);
        uint4 uh = make_uint4(pack_h2(hh[0], hh[1]), pack_h2(hh[2], hh[3]),
                              pack_h2(hh[4], hh[5]), pack_h2(hh[6], hh[7]));
        uint4 ul = make_uint4(pack_h2(ll[0], ll[1]), pack_h2(ll[2], ll[3]),
                              pack_h2(ll[4], ll[5]), pack_h2(ll[6], ll[7]));
        const int c = c0 + c2;
        *(uint4*)(drow + (((c)     ^ e) << 4)) = uh;
        *(uint4*)(drow + (((c ^ 4) ^ e) << 4)) = ul;
    }
}

// ---------------------------------------------------------------- merged prepass
// b in [0,16): E=CB@W slice compute + split. [16,80): W tiles. b==80: tvec.
// [81, 81+4096): X tiles.
__global__ void prepass_kernel(const float* __restrict__ X,
                               const float* __restrict__ W,
                               const float* __restrict__ B,
                               const float* __restrict__ CB) {
    __shared__ __align__(16) char st[TILE_B];
    const int b = blockIdx.x;
    const int tid = threadIdx.x, r = tid >> 1, h = tid & 1;

    if (b < 16) {
        // E[:, j0:j0+32] = CB(128x512) @ W(512x512) slice; thread: code r, half h
        const int j0 = b * 32;
        const float* cbr = CB + (size_t)r * D;
        const float* wp = W + j0 + h * 16;
        float4 e0 = {0,0,0,0}, e1 = e0, e2 = e0, e3 = e0;
        #pragma unroll 4
        for (int k = 0; k < D; ++k) {
            const float cv = cbr[k];
            const float4* wr = (const float4*)(wp + (size_t)k * D);
            float4 w0 = wr[0], w1 = wr[1], w2 = wr[2], w3 = wr[3];
            e0.x += cv * w0.x; e0.y += cv * w0.y; e0.z += cv * w0.z; e0.w += cv * w0.w;
            e1.x += cv * w1.x; e1.y += cv * w1.y; e1.z += cv * w1.z; e1.w += cv * w1.w;
            e2.x += cv * w2.x; e2.y += cv * w2.y; e2.z += cv * w2.z; e2.w += cv * w2.w;
            e3.x += cv * w3.x; e3.y += cv * w3.y; e3.z += cv * w3.z; e3.w += cv * w3.w;
        }
        const float4 v[4] = {e0, e1, e2, e3};
        split16(v, &st[r * 128], h * 2, r & 7);
        __syncthreads();
        char* dst = &g_esplit[b][0];
        #pragma unroll
        for (int k = 0; k < 4; ++k)
            *(uint4*)(dst + tid * 16 + k * 4096) = *(const uint4*)(st + tid * 16 + k * 4096);
        return;
    }
    if (b == 80) {
        const int c = tid >> 1;
        const float* cp = CB + (size_t)c * D + h * 256;
        const float* bp = B + h * 256;
        float s2 = 0.f, sb = 0.f;
        #pragma unroll 4
        for (int k = 0; k < 64; ++k) {
            float4 v = ((const float4*)cp)[k];
            float4 bv = ((const float4*)bp)[k];
            s2 += v.x * v.x + v.y * v.y + v.z * v.z + v.w * v.w;
            sb += v.x * bv.x + v.y * bv.y + v.z * bv.z + v.w * bv.w;
        }
        s2 += __shfl_xor_sync(0xffffffffu, s2, 1);
        sb += __shfl_xor_sync(0xffffffffu, sb, 1);
        if (!h) g_tvec[c] = s2 - 2.f * sb;
        return;
    }

    const float* src0;
    char* dst;
    if (b < 80) {
        const int bb = b - 16;
        const int ct = bb >> 4, s = bb & 15;
        src0 = W + (size_t)(ct * 128 + r) * D + s * 32 + h * 16;
        dst = &g_wsplit[ct][s][0];
    } else {
        const int bb = b - 81;
        const int rb = bb >> 4, s = bb & 15;
        src0 = X + (size_t)(rb * 128 + r) * D + s * 32 + h * 16;
        dst = &g_xsplit[rb][s][0];
    }
    float4 v[4];
    #pragma unroll
    for (int i = 0; i < 4; ++i) v[i] = ((const float4*)src0)[i];
    split16(v, &st[r * 128], h * 2, r & 7);
    __syncthreads();
    #pragma unroll
    for (int k = 0; k < 4; ++k)
        *(uint4*)(dst + tid * 16 + k * 4096) = *(const uint4*)(st + tid * 16 + k * 4096);
}

// ---------------------------------------------------------------- per-stage MMA (128x128x32, split-2)
DEVINL void stage_mma(u32 aT, int tid, float acc[4][4][4]) {
    const int lane = tid & 31, w = tid >> 5;
    const int mw = w >> 2, nw = w & 3;
    const int eL = lane & 7;
    const int rA = lane & 15, cAk = lane >> 4;
    const int rB0 = nw * 32 + ((lane >> 4) << 3) + (lane & 7);
    const int cBk = (lane >> 3) & 1;
    const u32 bT = aT + TILE_B;

    #pragma unroll
    for (int kk = 0; kk < 2; ++kk) {
        u32 ahi[4][4], alo[4][4], bhi[4][2], blo[4][2];
        const int swA = (kk * 2 + cAk) ^ eL;
        #pragma unroll
        for (int mb = 0; mb < 4; ++mb) {
            const u32 base = aT + (mw * 64 + mb * 16 + rA) * 128;
            ldsm4(ahi[mb][0], ahi[mb][1], ahi[mb][2], ahi[mb][3], base + (swA << 4));
            ldsm4(alo[mb][0], alo[mb][1], alo[mb][2], alo[mb][3], base + ((swA ^ 4) << 4));
        }
        const int swB = (kk * 2 + cBk) ^ eL;
        #pragma unroll
        for (int bp = 0; bp < 2; ++bp) {
            const u32 base = bT + (rB0 + bp * 16) * 128;
            u32 r0, r1, r2, r3;
            ldsm4(r0, r1, r2, r3, base + (swB << 4));
            bhi[bp*2][0] = r0; bhi[bp*2][1] = r1;
            bhi[bp*2+1][0] = r2; bhi[bp*2+1][1] = r3;
            ldsm4(r0, r1, r2, r3, base + ((swB ^ 4) << 4));
            blo[bp*2][0] = r0; blo[bp*2][1] = r1;
            blo[bp*2+1][0] = r2; blo[bp*2+1][1] = r3;
        }
        #pragma unroll
        for (int mb = 0; mb < 4; ++mb)
            #pragma unroll
            for (int nb = 0; nb < 4; ++nb) {
                mma_f16(acc[mb][nb], ahi[mb], bhi[nb]);
                mma_f16(acc[mb][nb], ahi[mb], blo[nb]);
                mma_f16(acc[mb][nb], alo[mb], bhi[nb]);
            }
    }
}

// ---------------------------------------------------------------- GEMM: Z = X W^T + b
__global__ void __launch_bounds__(256, 2)
gemm_hmma(const float* __restrict__ bias, float* __restrict__ Z)
{
    extern __shared__ char smc[];
    const u32 sb = smem_u32(smc);
    const int tid = threadIdx.x;
    const int ct = blockIdx.x, rb = blockIdx.y;      // ct fast -> X L2 reuse
    const int li = tid & 127;

    const char* srcBase = (tid < 128) ? &g_xsplit[rb][0][0] : &g_wsplit[ct][0][0];
    const u32 dstBase = ((tid < 128) ? 0u : (u32)TILE_B) + li * 16;

    #define G_ISSUE(s, buf) do {                                              \
        const char* _src = srcBase + (s) * TILE_B + li * 16;                  \
        const u32 _d = sb + (buf) * STAGE_B + dstBase;                        \
        _Pragma("unroll")                                                     \
        for (int _k = 0; _k < 8; ++_k) cp16(_d + _k * 2048, _src + _k * 2048);\
    } while (0)

    G_ISSUE(0, 0); cp_commit();
    G_ISSUE(1, 1); cp_commit();

    float acc[4][4][4] = {};
    int buf = 0;
    #pragma unroll 1
    for (int s = 0; s < 16; ++s) {
        cp_wait1();
        __syncthreads();
        int b2 = buf + 2; if (b2 >= 3) b2 -= 3;
        if (s + 2 < 16) G_ISSUE(s + 2, b2);
        cp_commit();
        stage_mma(sb + buf * STAGE_B, tid, acc);
        if (++buf == 3) buf = 0;
    }
    #undef G_ISSUE

    // ---- epilogue: stage z in smem, add bias, coalesced fp32 store (no split emit)
    cp_wait0();
    __syncthreads();

    float* zs = (float*)smc;                          // [128][132] = 67584 B
    const int lane = tid & 31, w = tid >> 5;
    const int mw = w >> 2, nw = w & 3;
    const int row0 = rb * 128, col0 = ct * 128;

    #pragma unroll
    for (int nb = 0; nb < 4; ++nb) {
        const int cb = nw * 32 + nb * 8 + (lane & 3) * 2;
        const float2 bv = *(const float2*)&bias[col0 + cb];
        #pragma unroll
        for (int mb = 0; mb < 4; ++mb) {
            const int rr = mw * 64 + mb * 16 + (lane >> 2);
            *(float2*)&zs[rr * 132 + cb] =
                make_float2(acc[mb][nb][0] + bv.x, acc[mb][nb][1] + bv.y);
            *(float2*)&zs[(rr + 8) * 132 + cb] =
                make_float2(acc[mb][nb][2] + bv.x, acc[mb][nb][3] + bv.y);
        }
    }
    __syncthreads();

    #pragma unroll
    for (int it = 0; it < 16; ++it) {
        const int idx = tid + it * 256;               // 4096 float4 slots
        const int rr = idx >> 5, c4 = (idx & 31) * 4;
        float4 v = *(float4*)&zs[rr * 132 + c4];
        *(float4*)&Z[(size_t)(row0 + rr) * D + col0 + c4] = v;
    }
}

// ---------------------------------------------------------------- VQ: X@E^T dots, argmin, gather
__global__ void __launch_bounds__(256, 2)
vq_hmma(const float* __restrict__ CB, float* __restrict__ Q1, float* __restrict__ Q2)
{
    extern __shared__ char smc[];
    float* scn  = (float*)(smc + LOOP_SMEM);
    ull*   wb   = (ull*)  (smc + LOOP_SMEM + 512);
    int*   bidx = (int*)  (smc + LOOP_SMEM + 512 + 4096);

    const u32 sb = smem_u32(smc);
    const int tid = threadIdx.x;
    const int rb = blockIdx.x;
    const int row0 = rb * 128;
    if (tid < NC) scn[tid] = g_tvec[tid];

    const int li = tid & 127;
    const char* srcBase = (tid < 128) ? &g_xsplit[rb][0][0] : &g_esplit[0][0];
    const u32 dstBase = ((tid < 128) ? 0u : (u32)TILE_B) + li * 16;

    #define V_ISSUE(s, buf) do {                                              \
        const char* _src = srcBase + (s) * TILE_B + li * 16;                  \
        const u32 _d = sb + (buf) * STAGE_B + dstBase;                        \
        _Pragma("unroll")                                                     \
        for (int _k = 0; _k < 8; ++_k) cp16(_d + _k * 2048, _src + _k * 2048);\
    } while (0)

    V_ISSUE(0, 0); cp_commit();
    V_ISSUE(1, 1); cp_commit();

    float acc[4][4][4] = {};
    int buf = 0;
    #pragma unroll 1
    for (int s = 0; s < 16; ++s) {
        cp_wait1();
        __syncthreads();
        int b2 = buf + 2; if (b2 >= 3) b2 -= 3;
        if (s + 2 < 16) V_ISSUE(s + 2, b2);
        cp_commit();
        stage_mma(sb + buf * STAGE_B, tid, acc);
        if (++buf == 3) buf = 0;
    }
    #undef V_ISSUE

    const int lane = tid & 31, w = tid >> 5;
    const int mw = w >> 2, nw = w & 3;

    #pragma unroll
    for (int mb = 0; mb < 4; ++mb) {
        #pragma unroll
        for (int rh = 0; rh < 2; ++rh) {
            ull best = ~0ull;
            #pragma unroll
            for (int nb = 0; nb < 4; ++nb) {
                #pragma unroll
                for (int j = 0; j < 2; ++j) {
                    const int code = nw * 32 + nb * 8 + (lane & 3) * 2 + j;
                    const float sc = fmaf(-2.f, acc[mb][nb][rh * 2 + j], scn[code]);
                    u32 o = __float_as_uint(sc);
                    o = (o & 0x80000000u) ? ~o : (o | 0x80000000u);
                    const ull key = ((ull)o << 32) | (u32)code;
                    if (key < best) best = key;
                }
            }
            ull t = __shfl_xor_sync(0xffffffffu, best, 1); if (t < best) best = t;
            t     = __shfl_xor_sync(0xffffffffu, best, 2); if (t < best) best = t;
            const int rowl = mw * 64 + mb * 16 + rh * 8 + (lane >> 2);
            if ((lane & 3) == 0) wb[rowl * 4 + nw] = best;
        }
    }
    __syncthreads();

    if (tid < 128) {
        ull m = wb[tid * 4];
        ull a = wb[tid * 4 + 1]; if (a < m) m = a;
        a = wb[tid * 4 + 2];     if (a < m) m = a;
        a = wb[tid * 4 + 3];     if (a < m) m = a;
        bidx[tid] = (int)(m & 0xffffffffu);
    }
    __syncthreads();

    for (int rr = w; rr < 128; rr += 8) {
        const int idx = bidx[rr];
        const float4* s4 = (const float4*)(CB + (size_t)idx * D);
        float4* o1 = (float4*)(Q1 + (size_t)(row0 + rr) * D);
        float4* o2 = (float4*)(Q2 + (size_t)(row0 + rr) * D);
        #pragma unroll
        for (int i = lane; i < D / 4; i += 32) {
            const float4 vv = s4[i];
            o1[i] = vv;
            o2[i] = vv;
        }
    }
}

// ---------------------------------------------------------------- launcher
extern "C" void kernel_launch(void* const* d_in, const int* in_sizes, int n_in,
                              void* d_out, int out_size)
{
    const float* x  = (const float*)d_in[0];
    const float* W  = (const float*)d_in[1];
    const float* b  = (const float*)d_in[2];
    const float* cb = (const float*)d_in[3];

    const int M = in_sizes[0] / D;            // 32768

    float* out = (float*)d_out;
    float* q1 = out;
    float* q2 = out + (size_t)M * D;
    float* z  = out + (size_t)2 * M * D;

    prepass_kernel<<<81 + (M / 128) * 16, 256>>>(x, W, b, cb);

    cudaFuncSetAttribute(gemm_hmma, cudaFuncAttributeMaxDynamicSharedMemorySize, LOOP_SMEM);
    gemm_hmma<<<dim3(D / 128, M / 128), 256, LOOP_SMEM>>>(b, z);

    cudaFuncSetAttribute(vq_hmma, cudaFuncAttributeMaxDynamicSharedMemorySize, VQ_SMEM);
    vq_hmma<<<M / 128, 256, VQ_SMEM>>>(cb, q1, q2);
}

// round 11
// speedup vs baseline: 1.8292x; 1.8292x over previous
#include <cuda_runtime.h>
#include <cuda_fp16.h>
#include <cstdint>
#include <cstddef>

#define DEVINL __device__ __forceinline__
using u32 = uint32_t;
using ull = unsigned long long;

constexpr int D  = 512;
constexpr int NC = 128;

constexpr int TILE_B   = 16384;            // one 128-row x 128B packed tile (hi|lo)
constexpr int STAGE_B  = 2 * TILE_B;       // A tile + B tile
constexpr int NSTAGE   = 3;
constexpr int LOOP_SMEM = NSTAGE * STAGE_B;            // 98304
constexpr int FUSED_SMEM = LOOP_SMEM + 512 + 4096 + 512;  // + tvec + wb + bidx

__device__ float g_tvec[NC];               // ||c||^2 - 2 b.c
__device__ float g_efp32[NC * D];          // E = CB @ W (fp32)
__device__ __align__(128) char g_xsplit[256][16][TILE_B];   // 64 MB
__device__ __align__(128) char g_wsplit[4][16][TILE_B];     // 1 MB
__device__ __align__(128) char g_esplit[16][TILE_B];        // 256 KB

// ---------------------------------------------------------------- helpers
DEVINL u32 smem_u32(const void* p) {
    u32 a;
    asm("{ .reg .u64 t; cvta.to.shared.u64 t, %1; cvt.u32.u64 %0, t; }"
        : "=r"(a) : "l"(p));
    return a;
}
DEVINL void ldsm4(u32& r0, u32& r1, u32& r2, u32& r3, u32 a) {
    asm volatile("ldmatrix.sync.aligned.m8n8.x4.shared.b16 {%0,%1,%2,%3}, [%4];"
                 : "=r"(r0), "=r"(r1), "=r"(r2), "=r"(r3) : "r"(a));
}
DEVINL void mma_f16(float c[4], const u32 a[4], const u32 b[2]) {
    asm volatile(
        "mma.sync.aligned.m16n8k16.row.col.f32.f16.f16.f32 "
        "{%0,%1,%2,%3},{%4,%5,%6,%7},{%8,%9},{%0,%1,%2,%3};"
        : "+f"(c[0]), "+f"(c[1]), "+f"(c[2]), "+f"(c[3])
        : "r"(a[0]), "r"(a[1]), "r"(a[2]), "r"(a[3]), "r"(b[0]), "r"(b[1]));
}
DEVINL u32 pack_h2(__half a, __half b) {
    __half2 h = __halves2half2(a, b);
    return *reinterpret_cast<u32*>(&h);
}
DEVINL void fsplit(float x, __half& h, __half& l) {
    h = __float2half_rn(x);
    l = __float2half_rn(x - __half2float(h));
}
DEVINL void cp16(u32 dst, const void* src) {
    asm volatile("cp.async.cg.shared.global [%0], [%1], 16;" :: "r"(dst), "l"(src));
}
DEVINL void cp_commit() { asm volatile("cp.async.commit_group;" ::: "memory"); }
DEVINL void cp_wait1()  { asm volatile("cp.async.wait_group 1;" ::: "memory"); }
DEVINL void cp_wait0()  { asm volatile("cp.async.wait_group 0;" ::: "memory"); }

// split 16 fp32 into 2 hi + 2 lo 16B chunks of a packed tile row.
// hi chunk c at ((c^e)<<4), lo at (((c^4)^e)<<4), e = row&7.
DEVINL void split16(const float4 v[4], char* drow, int c0, int e) {
    #pragma unroll
    for (int c2 = 0; c2 < 2; ++c2) {
        const float f[8] = { v[2*c2].x, v[2*c2].y, v[2*c2].z, v[2*c2].w,
                             v[2*c2+1].x, v[2*c2+1].y, v[2*c2+1].z, v[2*c2+1].w };
        __half hh[8], ll[8];
        #pragma unroll
        for (int j = 0; j < 8; ++j) fsplit(f[j], hh[j], ll[j]);
        uint4 uh = make_uint4(pack_h2(hh[0], hh[1]), pack_h2(hh[2], hh[3]),
                              pack_h2(hh[4], hh[5]), pack_h2(hh[6], hh[7]));
        uint4 ul = make_uint4(pack_h2(ll[0], ll[1]), pack_h2(ll[2], ll[3]),
                              pack_h2(ll[4], ll[5]), pack_h2(ll[6], ll[7]));
        const int c = c0 + c2;
        *(uint4*)(drow + (((c)     ^ e) << 4)) = uh;
        *(uint4*)(drow + (((c ^ 4) ^ e) << 4)) = ul;
    }
}

// ---------------------------------------------------------------- prepass 1
// b<256: E compute (coalesced/broadcast mapping). [256,320): W tiles. [320,4416): X tiles.
__global__ void prepass1_kernel(const float* __restrict__ X,
                                const float* __restrict__ W,
                                const float* __restrict__ CB) {
    __shared__ __align__(16) char st[TILE_B];
    const int b = blockIdx.x;
    const int tid = threadIdx.x;

    if (b < 256) {
        // E[r][c] = dot(CB[r,:], W[:,c]); r = b>>1, c = (b&1)*256 + tid
        const int r = b >> 1;
        const int c = (b & 1) * 256 + tid;
        const float* cbr = CB + (size_t)r * D;
        const float* wc  = W + c;
        float a0 = 0.f, a1 = 0.f, a2 = 0.f, a3 = 0.f;
        #pragma unroll 2
        for (int k = 0; k < D; k += 8) {
            a0 = fmaf(cbr[k + 0], wc[(size_t)(k + 0) * D], a0);
            a1 = fmaf(cbr[k + 1], wc[(size_t)(k + 1) * D], a1);
            a2 = fmaf(cbr[k + 2], wc[(size_t)(k + 2) * D], a2);
            a3 = fmaf(cbr[k + 3], wc[(size_t)(k + 3) * D], a3);
            a0 = fmaf(cbr[k + 4], wc[(size_t)(k + 4) * D], a0);
            a1 = fmaf(cbr[k + 5], wc[(size_t)(k + 5) * D], a1);
            a2 = fmaf(cbr[k + 6], wc[(size_t)(k + 6) * D], a2);
            a3 = fmaf(cbr[k + 7], wc[(size_t)(k + 7) * D], a3);
        }
        g_efp32[(size_t)r * D + c] = (a0 + a1) + (a2 + a3);
        return;
    }

    const int r = tid >> 1, h = tid & 1;
    const float* src0;
    char* dst;
    if (b < 320) {
        const int bb = b - 256;
        const int ct = bb >> 4, s = bb & 15;
        src0 = W + (size_t)(ct * 128 + r) * D + s * 32 + h * 16;
        dst = &g_wsplit[ct][s][0];
    } else {
        const int bb = b - 320;
        const int rb = bb >> 4, s = bb & 15;
        src0 = X + (size_t)(rb * 128 + r) * D + s * 32 + h * 16;
        dst = &g_xsplit[rb][s][0];
    }
    float4 v[4];
    #pragma unroll
    for (int i = 0; i < 4; ++i) v[i] = ((const float4*)src0)[i];
    split16(v, &st[r * 128], h * 2, r & 7);
    __syncthreads();
    #pragma unroll
    for (int k = 0; k < 4; ++k)
        *(uint4*)(dst + tid * 16 + k * 4096) = *(const uint4*)(st + tid * 16 + k * 4096);
}

// ---------------------------------------------------------------- prepass 2 (after E): E split + tvec
__global__ void prepass2_kernel(const float* __restrict__ B,
                                const float* __restrict__ CB) {
    __shared__ __align__(16) char st[TILE_B];
    const int b = blockIdx.x;
    const int tid = threadIdx.x, r = tid >> 1, h = tid & 1;

    if (b < 16) {
        const float* src0 = g_efp32 + (size_t)r * D + b * 32 + h * 16;
        float4 v[4];
        #pragma unroll
        for (int i = 0; i < 4; ++i) v[i] = ((const float4*)src0)[i];
        split16(v, &st[r * 128], h * 2, r & 7);
        __syncthreads();
        char* dst = &g_esplit[b][0];
        #pragma unroll
        for (int k = 0; k < 4; ++k)
            *(uint4*)(dst + tid * 16 + k * 4096) = *(const uint4*)(st + tid * 16 + k * 4096);
        return;
    }
    // tvec
    const int c = tid >> 1;
    const float* cp = CB + (size_t)c * D + h * 256;
    const float* bp = B + h * 256;
    float s2 = 0.f, sb = 0.f;
    #pragma unroll 4
    for (int k = 0; k < 64; ++k) {
        float4 v = ((const float4*)cp)[k];
        float4 bv = ((const float4*)bp)[k];
        s2 += v.x * v.x + v.y * v.y + v.z * v.z + v.w * v.w;
        sb += v.x * bv.x + v.y * bv.y + v.z * bv.z + v.w * bv.w;
    }
    s2 += __shfl_xor_sync(0xffffffffu, s2, 1);
    sb += __shfl_xor_sync(0xffffffffu, sb, 1);
    if (!h) g_tvec[c] = s2 - 2.f * sb;
}

// ---------------------------------------------------------------- per-stage MMA (128x128x32, split-2)
DEVINL void stage_mma(u32 aT, int tid, float acc[4][4][4]) {
    const int lane = tid & 31, w = tid >> 5;
    const int mw = w >> 2, nw = w & 3;
    const int eL = lane & 7;
    const int rA = lane & 15, cAk = lane >> 4;
    const int rB0 = nw * 32 + ((lane >> 4) << 3) + (lane & 7);
    const int cBk = (lane >> 3) & 1;
    const u32 bT = aT + TILE_B;

    #pragma unroll
    for (int kk = 0; kk < 2; ++kk) {
        u32 ahi[4][4], alo[4][4], bhi[4][2], blo[4][2];
        const int swA = (kk * 2 + cAk) ^ eL;
        #pragma unroll
        for (int mb = 0; mb < 4; ++mb) {
            const u32 base = aT + (mw * 64 + mb * 16 + rA) * 128;
            ldsm4(ahi[mb][0], ahi[mb][1], ahi[mb][2], ahi[mb][3], base + (swA << 4));
            ldsm4(alo[mb][0], alo[mb][1], alo[mb][2], alo[mb][3], base + ((swA ^ 4) << 4));
        }
        const int swB = (kk * 2 + cBk) ^ eL;
        #pragma unroll
        for (int bp = 0; bp < 2; ++bp) {
            const u32 base = bT + (rB0 + bp * 16) * 128;
            u32 r0, r1, r2, r3;
            ldsm4(r0, r1, r2, r3, base + (swB << 4));
            bhi[bp*2][0] = r0; bhi[bp*2][1] = r1;
            bhi[bp*2+1][0] = r2; bhi[bp*2+1][1] = r3;
            ldsm4(r0, r1, r2, r3, base + ((swB ^ 4) << 4));
            blo[bp*2][0] = r0; blo[bp*2][1] = r1;
            blo[bp*2+1][0] = r2; blo[bp*2+1][1] = r3;
        }
        #pragma unroll
        for (int mb = 0; mb < 4; ++mb)
            #pragma unroll
            for (int nb = 0; nb < 4; ++nb) {
                mma_f16(acc[mb][nb], ahi[mb], bhi[nb]);
                mma_f16(acc[mb][nb], ahi[mb], blo[nb]);
                mma_f16(acc[mb][nb], alo[mb], bhi[nb]);
            }
    }
}

// ---------------------------------------------------------------- fused GEMM + VQ
// grid (5, 256): ct<4 -> Z tile epilogue; ct==4 -> B=E, argmin + gather epilogue.
__global__ void __launch_bounds__(256, 2)
fused_hmma(const float* __restrict__ bias, const float* __restrict__ CB,
           float* __restrict__ Z, float* __restrict__ Q1, float* __restrict__ Q2)
{
    extern __shared__ char smc[];
    float* scn  = (float*)(smc + LOOP_SMEM);
    ull*   wb   = (ull*)  (smc + LOOP_SMEM + 512);
    int*   bidx = (int*)  (smc + LOOP_SMEM + 512 + 4096);

    const u32 sb = smem_u32(smc);
    const int tid = threadIdx.x;
    const int ct = blockIdx.x, rb = blockIdx.y;      // ct fast -> X L2 reuse
    const int li = tid & 127;

    if (ct == 4 && tid < NC) scn[tid] = g_tvec[tid];

    const char* srcBase = (tid < 128) ? &g_xsplit[rb][0][0]
                        : (ct < 4 ? &g_wsplit[ct][0][0] : &g_esplit[0][0]);
    const u32 dstBase = ((tid < 128) ? 0u : (u32)TILE_B) + li * 16;

    #define F_ISSUE(s, buf) do {                                              \
        const char* _src = srcBase + (s) * TILE_B + li * 16;                  \
        const u32 _d = sb + (buf) * STAGE_B + dstBase;                        \
        _Pragma("unroll")                                                     \
        for (int _k = 0; _k < 8; ++_k) cp16(_d + _k * 2048, _src + _k * 2048);\
    } while (0)

    F_ISSUE(0, 0); cp_commit();
    F_ISSUE(1, 1); cp_commit();

    float acc[4][4][4] = {};
    int buf = 0;
    #pragma unroll 1
    for (int s = 0; s < 16; ++s) {
        cp_wait1();
        __syncthreads();
        int b2 = buf + 2; if (b2 >= 3) b2 -= 3;
        if (s + 2 < 16) F_ISSUE(s + 2, b2);
        cp_commit();
        stage_mma(sb + buf * STAGE_B, tid, acc);
        if (++buf == 3) buf = 0;
    }
    #undef F_ISSUE

    cp_wait0();
    __syncthreads();

    const int lane = tid & 31, w = tid >> 5;
    const int mw = w >> 2, nw = w & 3;
    const int row0 = rb * 128;

    if (ct < 4) {
        // ---- Z epilogue: stage in smem, add bias, coalesced fp32 store
        float* zs = (float*)smc;                      // [128][132] = 67584 B
        const int col0 = ct * 128;
        #pragma unroll
        for (int nb = 0; nb < 4; ++nb) {
            const int cb = nw * 32 + nb * 8 + (lane & 3) * 2;
            const float2 bv = *(const float2*)&bias[col0 + cb];
            #pragma unroll
            for (int mb = 0; mb < 4; ++mb) {
                const int rr = mw * 64 + mb * 16 + (lane >> 2);
                *(float2*)&zs[rr * 132 + cb] =
                    make_float2(acc[mb][nb][0] + bv.x, acc[mb][nb][1] + bv.y);
                *(float2*)&zs[(rr + 8) * 132 + cb] =
                    make_float2(acc[mb][nb][2] + bv.x, acc[mb][nb][3] + bv.y);
            }
        }
        __syncthreads();
        #pragma unroll
        for (int it = 0; it < 16; ++it) {
            const int idx = tid + it * 256;           // 4096 float4 slots
            const int rr = idx >> 5, c4 = (idx & 31) * 4;
            float4 v = *(float4*)&zs[rr * 132 + c4];
            *(float4*)&Z[(size_t)(row0 + rr) * D + col0 + c4] = v;
        }
    } else {
        // ---- VQ epilogue: score = tvec[code] - 2*dot ; argmin ; gather
        #pragma unroll
        for (int mb = 0; mb < 4; ++mb) {
            #pragma unroll
            for (int rh = 0; rh < 2; ++rh) {
                ull best = ~0ull;
                #pragma unroll
                for (int nb = 0; nb < 4; ++nb) {
                    #pragma unroll
                    for (int j = 0; j < 2; ++j) {
                        const int code = nw * 32 + nb * 8 + (lane & 3) * 2 + j;
                        const float sc = fmaf(-2.f, acc[mb][nb][rh * 2 + j], scn[code]);
                        u32 o = __float_as_uint(sc);
                        o = (o & 0x80000000u) ? ~o : (o | 0x80000000u);
                        const ull key = ((ull)o << 32) | (u32)code;
                        if (key < best) best = key;
                    }
                }
                ull t = __shfl_xor_sync(0xffffffffu, best, 1); if (t < best) best = t;
                t     = __shfl_xor_sync(0xffffffffu, best, 2); if (t < best) best = t;
                const int rowl = mw * 64 + mb * 16 + rh * 8 + (lane >> 2);
                if ((lane & 3) == 0) wb[rowl * 4 + nw] = best;
            }
        }
        __syncthreads();

        if (tid < 128) {
            ull m = wb[tid * 4];
            ull a = wb[tid * 4 + 1]; if (a < m) m = a;
            a = wb[tid * 4 + 2];     if (a < m) m = a;
            a = wb[tid * 4 + 3];     if (a < m) m = a;
            bidx[tid] = (int)(m & 0xffffffffu);
        }
        __syncthreads();

        for (int rr = w; rr < 128; rr += 8) {
            const int idx = bidx[rr];
            const float4* s4 = (const float4*)(CB + (size_t)idx * D);
            float4* o1 = (float4*)(Q1 + (size_t)(row0 + rr) * D);
            float4* o2 = (float4*)(Q2 + (size_t)(row0 + rr) * D);
            #pragma unroll
            for (int i = lane; i < D / 4; i += 32) {
                const float4 vv = s4[i];
                o1[i] = vv;
                o2[i] = vv;
            }
        }
    }
}

// ---------------------------------------------------------------- launcher
extern "C" void kernel_launch(void* const* d_in, const int* in_sizes, int n_in,
                              void* d_out, int out_size)
{
    const float* x  = (const float*)d_in[0];
    const float* W  = (const float*)d_in[1];
    const float* b  = (const float*)d_in[2];
    const float* cb = (const float*)d_in[3];

    const int M = in_sizes[0] / D;            // 32768

    float* out = (float*)d_out;
    float* q1 = out;
    float* q2 = out + (size_t)M * D;
    float* z  = out + (size_t)2 * M * D;

    prepass1_kernel<<<320 + (M / 128) * 16, 256>>>(x, W, cb);
    prepass2_kernel<<<17, 256>>>(b, cb);

    cudaFuncSetAttribute(fused_hmma, cudaFuncAttributeMaxDynamicSharedMemorySize, FUSED_SMEM);
    fused_hmma<<<dim3(5, M / 128), 256, FUSED_SMEM>>>(b, cb, z, q1, q2);
}